// round 15
// baseline (speedup 1.0000x reference)
#include <cuda_runtime.h>

// SPU transformer bound propagation — pure elementwise over N=8388608. FINAL.
//
// Roofline verdict (14 rounds of evidence, 6 reproductions of this config):
//   traffic  : 4x64MiB in + 64MiB out = 320 MiB (information floor — all five
//              streams required, fp32 contract dtype, full-sector stores)
//   achieved : 6.6-6.7 TB/s sustained at nominal clocks = B300 LTS chip cap
//              (~6300 B/cyc, path-independent: TMA would measure identically)
//   kernel   : 45.6-46.7 us nominal (49-50 us on low-clock holds);
//              bench 51.23-51.71, fast cluster 51.23-51.36
//
// Configuration (best-measured, reproduced on 6 independent holds):
//   flat launch, 256 thr/blk, one float4 per array per thread
//   (4x independent LDG.128 + STG.128), __ldcs/__stcs evict-first
//   (zero-reuse stream), plain IEEE division, 32 regs, occ ~85%,
//   DRAM 83-85% = the binding pipe; all other pipes <50% at nominal clock.
//
// Tried and rejected with measurements:
//   unroll x4 front-batched loads : 80 regs, occ 34%, DRAM 78% -> REGRESSED
//   persistent single-wave loop   : 44 regs, occ 49%, DRAM 72% -> REGRESSED
//   block sizes 128 / 512         : within +-1% of 256         -> NEUTRAL
//   __fdividef                    : fma 21->16%, no wallclock  -> reverted

__device__ __forceinline__ float spu_f(float x) {
    // x>=0: x*x - 0.5 ; x<0: sigmoid(-x) - 1 = -e^x / (1 + e^x)
    float ex = __expf(x);
    float negv = -ex / (1.0f + ex);
    float posv = fmaf(x, x, -0.5f);
    return x >= 0.0f ? posv : negv;
}

__device__ __forceinline__ void spu_elem(
    float l, float u,          // bounds
    float p1l, float p1u,      // slopes_prev
    float q1l, float q1u,      // shifts_prev
    float b0l, float b0u,      // bounds_prev
    float& out_lo, float& out_hi)
{
    float sl = spu_f(l);
    float su = spu_f(u);

    bool neg   = (u <= 0.0f);
    bool pos   = (l >= 0.0f);
    bool cross = !(neg || pos);

    float slope = (su - sl) / (u - l);   // u-l >= 0.02, safe

    float s0 = neg ? slope : 0.0f;
    float s1 = neg ? 0.0f  : slope;     // pos|cross == !neg

    bool neg_slope = (slope < 0.0f);
    float lo = neg_slope ? su : sl;
    float hi = neg_slope ? sl : su;
    lo = cross ? -0.5f : lo;

    float sh1 = fmaf(-s1, u, su);
    float sh0 = fmaf(-s0, l, sl);
    sh0 = cross ? -0.5f : sh0;
    sh1 = neg   ? sl    : sh1;

    float s1p = fmaxf(s1, 0.0f), s1n = fminf(s1, 0.0f);
    float s0p = fmaxf(s0, 0.0f), s0n = fminf(s0, 0.0f);

    float UBM = fmaf(s1p, p1u, s1n * p1l);
    float UBV = fmaf(s1p, q1u, fmaf(s1n, q1l, sh1));
    float LBM = fmaf(s0p, p1l, s0n * p1u);
    float LBV = fmaf(s0n, q1l, fmaf(s0p, q1u, sh0));

    float lower = fmaf(fmaxf(LBM, 0.0f), b0l, fmaf(fminf(LBM, 0.0f), b0u, LBV));
    float upper = fmaf(fmaxf(UBM, 0.0f), b0u, fmaf(fminf(UBM, 0.0f), b0l, UBV));

    out_lo = (lower > lo) ? lower : lo;
    out_hi = (upper < hi) ? upper : hi;
}

__global__ void __launch_bounds__(256)
spu_kernel(const float4* __restrict__ bounds,
           const float4* __restrict__ slopes_prev,
           const float4* __restrict__ shifts_prev,
           const float4* __restrict__ bounds_prev,
           float4* __restrict__ out,
           int n_vec)   // n_vec = N/2 float4s, each covering 2 elements
{
    int i = blockIdx.x * blockDim.x + threadIdx.x;
    if (i >= n_vec) return;

    float4 b  = __ldcs(&bounds[i]);
    float4 sp = __ldcs(&slopes_prev[i]);
    float4 sh = __ldcs(&shifts_prev[i]);
    float4 bp = __ldcs(&bounds_prev[i]);

    float4 r;
    spu_elem(b.x, b.y, sp.x, sp.y, sh.x, sh.y, bp.x, bp.y, r.x, r.y);
    spu_elem(b.z, b.w, sp.z, sp.w, sh.z, sh.w, bp.z, bp.w, r.z, r.w);

    __stcs(&out[i], r);
}

extern "C" void kernel_launch(void* const* d_in, const int* in_sizes, int n_in,
                              void* d_out, int out_size) {
    // metadata order: bounds (N,2), slopes_prev (N,2), shifts_prev (N,2), bounds_prev (N,2)
    const float4* bounds      = (const float4*)d_in[0];
    const float4* slopes_prev = (const float4*)d_in[1];
    const float4* shifts_prev = (const float4*)d_in[2];
    const float4* bounds_prev = (const float4*)d_in[3];
    float4* out = (float4*)d_out;

    int n_floats = in_sizes[0];          // N*2
    int n_vec = n_floats / 4;            // float4 count (N*2 divisible by 4)

    int threads = 256;
    int blocks = (n_vec + threads - 1) / threads;
    spu_kernel<<<blocks, threads>>>(bounds, slopes_prev, shifts_prev, bounds_prev, out, n_vec);
}

// round 16
// speedup vs baseline: 1.0305x; 1.0305x over previous
#include <cuda_runtime.h>

// SPU transformer bound propagation — pure elementwise over N=8388608. FINAL.
//
// Roofline verdict (15 rounds, 7 reproductions of this exact source):
//   traffic  : 4x64MiB in + 64MiB out = 320 MiB (information floor — all five
//              streams required, fp32 contract dtype, full-sector stores)
//   achieved : 6.5-6.7 TB/s sustained = B300 LTS chip cap (~6300 B/cyc,
//              path-independent: TMA/cp.async would measure identically)
//   kernel   : 45.6-47.2 us (hold-clock dependent); bench fast cluster
//              51.23-51.36, slow-clock holds up to 51.97
//
// Configuration: flat launch, 256 thr/blk, one float4 per array per thread
// (4x independent LDG.128 + STG.128), __ldcs/__stcs evict-first (zero-reuse
// stream), plain IEEE division, 32 regs, occ ~85%, DRAM 83-85% = binding pipe.
//
// Tried and rejected with measurements:
//   unroll x4 front-batched loads : 80 regs, occ 34%, DRAM 78% -> REGRESSED
//   persistent single-wave loop   : 44 regs, occ 49%, DRAM 72% -> REGRESSED
//   block sizes 128 / 512         : within +-1% of 256         -> NEUTRAL
//   __fdividef                    : fma 21->16%, no wallclock  -> reverted

__device__ __forceinline__ float spu_f(float x) {
    // x>=0: x*x - 0.5 ; x<0: sigmoid(-x) - 1 = -e^x / (1 + e^x)
    float ex = __expf(x);
    float negv = -ex / (1.0f + ex);
    float posv = fmaf(x, x, -0.5f);
    return x >= 0.0f ? posv : negv;
}

__device__ __forceinline__ void spu_elem(
    float l, float u,          // bounds
    float p1l, float p1u,      // slopes_prev
    float q1l, float q1u,      // shifts_prev
    float b0l, float b0u,      // bounds_prev
    float& out_lo, float& out_hi)
{
    float sl = spu_f(l);
    float su = spu_f(u);

    bool neg   = (u <= 0.0f);
    bool pos   = (l >= 0.0f);
    bool cross = !(neg || pos);

    float slope = (su - sl) / (u - l);   // u-l >= 0.02, safe

    float s0 = neg ? slope : 0.0f;
    float s1 = neg ? 0.0f  : slope;     // pos|cross == !neg

    bool neg_slope = (slope < 0.0f);
    float lo = neg_slope ? su : sl;
    float hi = neg_slope ? sl : su;
    lo = cross ? -0.5f : lo;

    float sh1 = fmaf(-s1, u, su);
    float sh0 = fmaf(-s0, l, sl);
    sh0 = cross ? -0.5f : sh0;
    sh1 = neg   ? sl    : sh1;

    float s1p = fmaxf(s1, 0.0f), s1n = fminf(s1, 0.0f);
    float s0p = fmaxf(s0, 0.0f), s0n = fminf(s0, 0.0f);

    float UBM = fmaf(s1p, p1u, s1n * p1l);
    float UBV = fmaf(s1p, q1u, fmaf(s1n, q1l, sh1));
    float LBM = fmaf(s0p, p1l, s0n * p1u);
    float LBV = fmaf(s0n, q1l, fmaf(s0p, q1u, sh0));

    float lower = fmaf(fmaxf(LBM, 0.0f), b0l, fmaf(fminf(LBM, 0.0f), b0u, LBV));
    float upper = fmaf(fmaxf(UBM, 0.0f), b0u, fmaf(fminf(UBM, 0.0f), b0l, UBV));

    out_lo = (lower > lo) ? lower : lo;
    out_hi = (upper < hi) ? upper : hi;
}

__global__ void __launch_bounds__(256)
spu_kernel(const float4* __restrict__ bounds,
           const float4* __restrict__ slopes_prev,
           const float4* __restrict__ shifts_prev,
           const float4* __restrict__ bounds_prev,
           float4* __restrict__ out,
           int n_vec)   // n_vec = N/2 float4s, each covering 2 elements
{
    int i = blockIdx.x * blockDim.x + threadIdx.x;
    if (i >= n_vec) return;

    float4 b  = __ldcs(&bounds[i]);
    float4 sp = __ldcs(&slopes_prev[i]);
    float4 sh = __ldcs(&shifts_prev[i]);
    float4 bp = __ldcs(&bounds_prev[i]);

    float4 r;
    spu_elem(b.x, b.y, sp.x, sp.y, sh.x, sh.y, bp.x, bp.y, r.x, r.y);
    spu_elem(b.z, b.w, sp.z, sp.w, sh.z, sh.w, bp.z, bp.w, r.z, r.w);

    __stcs(&out[i], r);
}

extern "C" void kernel_launch(void* const* d_in, const int* in_sizes, int n_in,
                              void* d_out, int out_size) {
    // metadata order: bounds (N,2), slopes_prev (N,2), shifts_prev (N,2), bounds_prev (N,2)
    const float4* bounds      = (const float4*)d_in[0];
    const float4* slopes_prev = (const float4*)d_in[1];
    const float4* shifts_prev = (const float4*)d_in[2];
    const float4* bounds_prev = (const float4*)d_in[3];
    float4* out = (float4*)d_out;

    int n_floats = in_sizes[0];          // N*2
    int n_vec = n_floats / 4;            // float4 count (N*2 divisible by 4)

    int threads = 256;
    int blocks = (n_vec + threads - 1) / threads;
    spu_kernel<<<blocks, threads>>>(bounds, slopes_prev, shifts_prev, bounds_prev, out, n_vec);
}